// round 8
// baseline (speedup 1.0000x reference)
#include <cuda_runtime.h>
#include <cstdint>

// MQCCLayer == depthwise 3x3 conv with F=2 shared unit-norm filters.
// Normalization cancels (conv is linear); channel slice is a no-op (C*F==8).
// out[b, c*2+f, h, w] = sum_ij x[b,c,h+i-1,w+j-1] * W[f,i,j],
// W[f] = angles[f]/||angles[f]||.
//
// Persistent-strip version: 64 output rows per block -> 1024 blocks = ONE
// wave (7 CTAs/SM x 148 SMs). A 14-row smem ring is fed by cp.async, 2 rows
// ahead of compute (wait_group 4 keeps exactly groups <= k+1 landed). The
// load stream never drains across the strip, so DRAM reads, FFMAs and output
// writes stay mixed; halo read amp drops to 66/64; no wave transitions.
// Ring=14 gives a 2-iteration cushion: slots overwritten at iter k were last
// read at iter k-2, strictly before the iter k-1 barrier -> no WAR race.

#define NB 32
#define NC 4
#define NH 512
#define NW 512
#define STRIP 64             // output rows per block
#define RING 14              // smem ring rows
#define SPAD 4               // front pad so col x lives at smem idx x+SPAD
#define SROW (SPAD + NW + 4) // 520 floats per smem row

__global__ void __launch_bounds__(128, 7)
mqcc_conv(const float* __restrict__ x, const float* __restrict__ angles,
          float* __restrict__ out) {
    __shared__ float sm[RING * SROW];
    const int t = threadIdx.x;
    const int bc = blockIdx.y;              // b*NC + c
    const int r0 = blockIdx.x * STRIP;      // first output row of this strip
    const float* __restrict__ xin = x + (size_t)bc * (NH * NW);

    // Zero left/right halo pads of all ring rows (never overwritten after).
    if (t < 2 * RING) {
        int i = t >> 1, side = t & 1;
        *reinterpret_cast<float4*>(&sm[i * SROW + side * (SPAD + NW)]) =
            make_float4(0.f, 0.f, 0.f, 0.f);
    }

    // cp.async one input row (s relative to strip) into a ring slot.
    // OOB rows use src-size 0 => zero-fill.
    const uint32_t sbase =
        (uint32_t)__cvta_generic_to_shared(sm) + (SPAD + 4 * t) * 4u;
    auto issue_row = [&](int s, int slot) {
        int gr = r0 + s;
        bool inb = (unsigned)gr < (unsigned)NH;
        const float* ga = xin + (size_t)(inb ? gr : 0) * NW + 4 * t;
        uint32_t sa = sbase + (uint32_t)slot * (SROW * 4u);
        int sz = inb ? 16 : 0;
        asm volatile("cp.async.cg.shared.global [%0], [%1], 16, %2;"
                     :: "r"(sa), "l"(ga), "r"(sz));
    };

    // Prologue: groups 0..4 stage rows -1..8 (slot(s) = (s+1) % RING).
#pragma unroll
    for (int g = 0; g < 5; g++) {
        issue_row(2 * g - 1, 2 * g);
        issue_row(2 * g,     2 * g + 1);
        asm volatile("cp.async.commit_group;");
    }

    // Normalized weights, recomputed per thread while copies are in flight.
    float w[18];
#pragma unroll
    for (int f = 0; f < 2; f++) {
        float s = 0.f;
#pragma unroll
        for (int i = 0; i < 9; i++) {
            float v = __ldg(&angles[f * 9 + i]);
            w[f * 9 + i] = v;
            s += v * v;
        }
        float inv = rsqrtf(s);
        inv = inv * (1.5f - 0.5f * s * inv * inv);   // NR step
#pragma unroll
        for (int i = 0; i < 9; i++) w[f * 9 + i] *= inv;
    }

    // Sliding 3-row register window of 6 cols (c0-1..c0+4), c0 = 4t.
    // W[(s+1)%3] holds input row s.
    float W[3][6];
    auto load_row = [&](int slot, float* d) {
        const float* s = &sm[slot * SROW + SPAD + 4 * t];
        float4 M = *reinterpret_cast<const float4*>(s);
        d[0] = s[-1];
        d[1] = M.x; d[2] = M.y; d[3] = M.z; d[4] = M.w;
        d[5] = s[4];
    };

    const int b = bc >> 2, c = bc & 3;
    float* __restrict__ o0 =
        out + ((size_t)(b * 8 + c * 2) * NH + r0) * NW + 4 * t;
    float* __restrict__ o1 = o0 + (size_t)NH * NW;

    int sl_ld = 2;    // slot of row 2k+1 at k=0:  (2k+2) % RING
    int sl_is = 10;   // slot of row 2k+9 at k=0:  (2k+10) % RING

#pragma unroll 3
    for (int k = 0; k < STRIP / 2; k++) {
        // Issue group k+5 (rows 2k+9, 2k+10); empty group at the tail.
        int s0 = 2 * k + 9;
        if (s0 <= STRIP) issue_row(s0, sl_is);
        int sl2 = sl_is + 1; if (sl2 == RING) sl2 = 0;
        if (s0 + 1 <= STRIP) issue_row(s0 + 1, sl2);
        sl_is += 2; if (sl_is >= RING) sl_is -= RING;
        asm volatile("cp.async.commit_group;");
        // Groups <= k+1 landed -> input rows <= 2k+2 present.
        asm volatile("cp.async.wait_group 4;" ::: "memory");
        __syncthreads();

        if (k == 0) { load_row(0, W[0]); load_row(1, W[1]); }

#pragma unroll
        for (int rr = 0; rr < 2; rr++) {
            const int r = 2 * k + rr;
            load_row(sl_ld, W[(r + 2) % 3]);
            sl_ld++; if (sl_ld == RING) sl_ld = 0;

            float a0 = 0.f, a1 = 0.f, a2 = 0.f, a3 = 0.f;  // filter 0
            float b0 = 0.f, b1 = 0.f, b2 = 0.f, b3 = 0.f;  // filter 1
#pragma unroll
            for (int ir = 0; ir < 3; ir++) {
                const float* Wr = W[(r + ir) % 3];
                const float* w0 = &w[ir * 3];
                const float* w1 = &w[9 + ir * 3];
#pragma unroll
                for (int j = 0; j < 3; j++) {
                    float f0 = w0[j], f1 = w1[j];
                    a0 = fmaf(f0, Wr[j + 0], a0);
                    a1 = fmaf(f0, Wr[j + 1], a1);
                    a2 = fmaf(f0, Wr[j + 2], a2);
                    a3 = fmaf(f0, Wr[j + 3], a3);
                    b0 = fmaf(f1, Wr[j + 0], b0);
                    b1 = fmaf(f1, Wr[j + 1], b1);
                    b2 = fmaf(f1, Wr[j + 2], b2);
                    b3 = fmaf(f1, Wr[j + 3], b3);
                }
            }
            *reinterpret_cast<float4*>(o0) = make_float4(a0, a1, a2, a3);
            *reinterpret_cast<float4*>(o1) = make_float4(b0, b1, b2, b3);
            o0 += NW;
            o1 += NW;
        }
    }
}

extern "C" void kernel_launch(void* const* d_in, const int* in_sizes, int n_in,
                              void* d_out, int out_size) {
    const float* x = (const float*)d_in[0];        // (32, 4, 512, 512) f32
    const float* angles = (const float*)d_in[1];   // (2, 3, 3) f32
    float* out = (float*)d_out;                    // (32, 8, 512, 512) f32

    dim3 grid(NH / STRIP, NB * NC);                // 8 x 128 = 1024 blocks
    mqcc_conv<<<grid, 128>>>(x, angles, out);
}

// round 9
// speedup vs baseline: 1.2152x; 1.2152x over previous
#include <cuda_runtime.h>
#include <cstdint>

// MQCCLayer == depthwise 3x3 conv with F=2 shared unit-norm filters.
// Normalization cancels (conv is linear); channel slice is a no-op (C*F==8).
// out[b, c*2+f, h, w] = sum_ij x[b,c,h+i-1,w+j-1] * W[f,i,j],
// W[f] = angles[f]/||angles[f]||.
//
// Best-measured structure (R2: phased smem tile, 128 thr, 8 rows/block,
// 8 blocks/SM) with 256-bit input loads (halves LDG instruction count;
// sm_103 requires the .v8.b32 form for L2 hints). Stores are PLAIN st.global
// — evict-first streaming stores measurably cost ~2us on this kernel
// (R3/R7 vs R2), so they are reverted.

#define NB 32
#define NC 4
#define NH 512
#define NW 512
#define BROWS 8              // output rows per block
#define SPAD 4               // front pad so col x lives at smem idx x+SPAD
#define SROW (SPAD + NW + 4) // 520 floats per smem row

__global__ void __launch_bounds__(128, 8)
mqcc_conv(const float* __restrict__ x, const float* __restrict__ angles,
          float* __restrict__ out) {
    __shared__ float sm[(BROWS + 2) * SROW];
    const int t = threadIdx.x;
    const int bc = blockIdx.y;              // b*NC + c
    const int r0 = blockIdx.x * BROWS;      // first output row of this block
    const float* __restrict__ xin = x + (size_t)bc * (NH * NW);

    // Stage BROWS+2 input rows: each thread loads 8 floats (one 256-bit LDG),
    // 128 threads cover 2 rows per iteration -> 5 iterations for 10 rows.
    {
        const int half = t >> 6;            // 0/1: which row of the pair
        const int c8 = (t & 63) * 8;        // col
#pragma unroll
        for (int i = 0; i < (BROWS + 2) / 2; i++) {
            int sr = 2 * i + half;
            int gr = r0 - 1 + sr;
            float v0 = 0.f, v1 = 0.f, v2 = 0.f, v3 = 0.f;
            float v4 = 0.f, v5 = 0.f, v6 = 0.f, v7 = 0.f;
            if ((unsigned)gr < (unsigned)NH) {
                const float* p = xin + (size_t)gr * NW + c8;
                asm("ld.global.nc.L2::evict_last.v8.b32 "
                    "{%0,%1,%2,%3,%4,%5,%6,%7}, [%8];"
                    : "=f"(v0), "=f"(v1), "=f"(v2), "=f"(v3),
                      "=f"(v4), "=f"(v5), "=f"(v6), "=f"(v7)
                    : "l"(p));
            }
            float* s = &sm[sr * SROW + SPAD + c8];
            *reinterpret_cast<float4*>(s)     = make_float4(v0, v1, v2, v3);
            *reinterpret_cast<float4*>(s + 4) = make_float4(v4, v5, v6, v7);
        }
    }
    // Zero halos: 10 rows x {left idx 0..3, right idx 516..519}
    if (t < 2 * (BROWS + 2)) {
        int i = t >> 1, side = t & 1;
        *reinterpret_cast<float4*>(&sm[i * SROW + side * (SPAD + NW)]) =
            make_float4(0.f, 0.f, 0.f, 0.f);
    }

    // Normalized weights, recomputed per thread (L2-cached loads, 2 rsqrt),
    // overlapping the in-flight staging loads.
    float w[18];
#pragma unroll
    for (int f = 0; f < 2; f++) {
        float s = 0.f;
#pragma unroll
        for (int i = 0; i < 9; i++) {
            float v = __ldg(&angles[f * 9 + i]);
            w[f * 9 + i] = v;
            s += v * v;
        }
        float inv = rsqrtf(s);
        inv = inv * (1.5f - 0.5f * s * inv * inv);   // NR step
#pragma unroll
        for (int i = 0; i < 9; i++) w[f * 9 + i] *= inv;
    }
    __syncthreads();

    // Sliding 3-row window of 6 input cols (c0-1 .. c0+4), c0 = 4t.
    float W[3][6];
    auto load_row = [&](int i, float* d) {
        const float* s = &sm[i * SROW + SPAD + 4 * t];
        float4 M = *reinterpret_cast<const float4*>(s);
        d[0] = s[-1];
        d[1] = M.x; d[2] = M.y; d[3] = M.z; d[4] = M.w;
        d[5] = s[4];
    };
    load_row(0, W[0]);
    load_row(1, W[1]);

    const int b = bc >> 2, c = bc & 3;
    float* __restrict__ o0 =
        out + ((size_t)(b * 8 + c * 2) * NH + r0) * NW + 4 * t;
    float* __restrict__ o1 = o0 + (size_t)NH * NW;

#pragma unroll
    for (int r = 0; r < BROWS; r++) {
        load_row(r + 2, W[(r + 2) % 3]);
        float a0 = 0.f, a1 = 0.f, a2 = 0.f, a3 = 0.f;   // filter 0, cols 0..3
        float b0 = 0.f, b1 = 0.f, b2 = 0.f, b3 = 0.f;   // filter 1, cols 0..3
#pragma unroll
        for (int ir = 0; ir < 3; ir++) {
            const float* Wr = W[(r + ir) % 3];
            const float* w0 = &w[ir * 3];
            const float* w1 = &w[9 + ir * 3];
#pragma unroll
            for (int j = 0; j < 3; j++) {
                float f0 = w0[j], f1 = w1[j];
                a0 = fmaf(f0, Wr[j + 0], a0);
                a1 = fmaf(f0, Wr[j + 1], a1);
                a2 = fmaf(f0, Wr[j + 2], a2);
                a3 = fmaf(f0, Wr[j + 3], a3);
                b0 = fmaf(f1, Wr[j + 0], b0);
                b1 = fmaf(f1, Wr[j + 1], b1);
                b2 = fmaf(f1, Wr[j + 2], b2);
                b3 = fmaf(f1, Wr[j + 3], b3);
            }
        }
        // Plain stores: measurably faster than streaming (.cs) on this kernel.
        *reinterpret_cast<float4*>(o0) = make_float4(a0, a1, a2, a3);
        *reinterpret_cast<float4*>(o1) = make_float4(b0, b1, b2, b3);
        o0 += NW;
        o1 += NW;
    }
}

extern "C" void kernel_launch(void* const* d_in, const int* in_sizes, int n_in,
                              void* d_out, int out_size) {
    const float* x = (const float*)d_in[0];        // (32, 4, 512, 512) f32
    const float* angles = (const float*)d_in[1];   // (2, 3, 3) f32
    float* out = (float*)d_out;                    // (32, 8, 512, 512) f32

    dim3 grid(NH / BROWS, NB * NC);
    mqcc_conv<<<grid, 128>>>(x, angles, out);
}